// round 15
// baseline (speedup 1.0000x reference)
#include <cuda_runtime.h>
#include <cuda_bf16.h>
#include <cuda_fp16.h>
#include <cstdint>

#define B_ROWS 16384
#define NDIM   4096
#define KDIM   784
#define TOPK   64
#define KPAD   2368        // 3*784 = 2352 padded to 2368 = 37*64
#define KCHUNKS 37         // KPAD / 64
#define KPADB  (KPAD * 2)  // row bytes of bf16 expanded arrays

// ---- scratch (static device globals; no allocations allowed) ----
__device__ __nv_bfloat16 g_X3[(size_t)B_ROWS * KPAD];   // 77.6 MB
__device__ __nv_bfloat16 g_W3[(size_t)NDIM * KPAD];     // 19.4 MB
__device__ float  g_Wt[NDIM * KDIM];                    // fp32 W^T (recompute)
__device__ __half g_Wh[NDIM * KDIM];                    // fp16 W^T (decoder)
__device__ int    g_total;

// ================= PTX helpers =================
__device__ __forceinline__ uint32_t smem_to_u32(const void* p) {
    uint32_t a;
    asm("{ .reg .u64 t; cvta.to.shared.u64 t, %1; cvt.u32.u64 %0, t; }"
        : "=r"(a) : "l"(p));
    return a;
}
__device__ __forceinline__ void cp16(uint32_t dst, const void* src) {
    asm volatile("cp.async.cg.shared.global [%0], [%1], 16;" :: "r"(dst), "l"(src));
}
#define CP_COMMIT() asm volatile("cp.async.commit_group;" ::: "memory")
#define CP_WAIT1()  asm volatile("cp.async.wait_group 1;" ::: "memory")
#define CP_WAIT0()  asm volatile("cp.async.wait_group 0;" ::: "memory")

__device__ __forceinline__ void ldsm_x4(uint32_t* r, uint32_t addr) {
    asm volatile("ldmatrix.sync.aligned.m8n8.x4.shared.b16 {%0,%1,%2,%3}, [%4];"
                 : "=r"(r[0]), "=r"(r[1]), "=r"(r[2]), "=r"(r[3]) : "r"(addr));
}
__device__ __forceinline__ void mma_bf16(float* c, const uint32_t* a,
                                         uint32_t b0, uint32_t b1) {
    asm volatile(
        "mma.sync.aligned.m16n8k16.row.col.f32.bf16.bf16.f32 "
        "{%0,%1,%2,%3}, {%4,%5,%6,%7}, {%8,%9}, {%0,%1,%2,%3};"
        : "+f"(c[0]), "+f"(c[1]), "+f"(c[2]), "+f"(c[3])
        : "r"(a[0]), "r"(a[1]), "r"(a[2]), "r"(a[3]), "r"(b0), "r"(b1));
}

// ================= bf16 2-limb split =================
__device__ __forceinline__ void split2(float a, __nv_bfloat16& h0, __nv_bfloat16& h1) {
    h0 = __float2bfloat16(a);
    h1 = __float2bfloat16(a - __bfloat162float(h0));
}

// ---------------- P0: split x -> X3 ----------------
__global__ __launch_bounds__(256) void split_x(const float* __restrict__ x) {
    int idx = blockIdx.x * 256 + threadIdx.x;
    int m = idx / 394;
    int u = idx - m * 394;
    if (m >= B_ROWS) return;
    char* rowp = (char*)g_X3 + (size_t)m * KPADB;
    if (u < 392) {
        int k = 2 * u;
        float2 xv = *(const float2*)(x + (size_t)m * KDIM + k);
        __nv_bfloat16 a0, a1, c0, c1;
        split2(xv.x, a0, a1);
        split2(xv.y, c0, c1);
        __nv_bfloat162* p = (__nv_bfloat162*)(rowp + 12 * u);
        p[0] = __halves2bfloat162(a0, a1);
        p[1] = __halves2bfloat162(a0, c0);
        p[2] = __halves2bfloat162(c1, c0);
    } else {
        *(uint4*)(rowp + 4704 + (u - 392) * 16) = make_uint4(0, 0, 0, 0);
    }
}

// ---------------- P1: split W -> W3 + fp32/fp16 transposes ----------------
__global__ __launch_bounds__(256) void split_wt(const float* __restrict__ W) {
    __shared__ float tile[32][65];
    const int n0  = blockIdx.x * 64;
    const int k0  = blockIdx.y * 32;
    const int tid = threadIdx.x;

    {
        const int c  = tid & 63;
        const int r0 = tid >> 6;
#pragma unroll
        for (int i = 0; i < 8; i++) {
            int r = r0 + 4 * i;
            int k = k0 + r;
            tile[r][c] = (k < KDIM) ? W[(size_t)k * NDIM + n0 + c] : 0.0f;
        }
    }
    __syncthreads();

    const int wrp  = tid >> 5;
    const int lane = tid & 31;
#pragma unroll
    for (int it = 0; it < 8; it++) {
        const int nl = wrp * 8 + it;
        const int n  = n0 + nl;
        char* rowp = (char*)g_W3 + (size_t)n * KPADB;

        if (k0 + lane < KDIM) {
            float wv = tile[lane][nl];
            g_Wt[(size_t)n * KDIM + k0 + lane] = wv;
            g_Wh[(size_t)n * KDIM + k0 + lane] = __float2half(wv);
        }

#pragma unroll
        for (int rr = 0; rr < 2; rr++) {
            int w = lane + 32 * rr;
            if (w < 48 && (k0 * 6 + w * 4) < KPADB) {
                int p = w / 3, j = w - 3 * p;
                float w0 = tile[2 * p][nl];
                float w1 = tile[2 * p + 1][nl];
                __nv_bfloat16 b0, b1, d0, d1;
                split2(w0, b0, b1);
                split2(w1, d0, d1);
                __nv_bfloat162 val;
                if (j == 0)      val = __halves2bfloat162(b0, b0);
                else if (j == 1) val = __halves2bfloat162(b1, d0);
                else             val = __halves2bfloat162(d0, d1);
                *(__nv_bfloat162*)(rowp + k0 * 6 + w * 4) = val;
            }
        }
    }
    if (blockIdx.x == 0 && blockIdx.y == 0 && tid == 0) g_total = 0;
}

// ---------------- K1: encoder GEMM (byte-identical to measured-best) -------
#define PITCH  144u
#define ASTG   (64u * PITCH)         // 9216
#define BSTG   (256u * PITCH)        // 36864
#define STG    (ASTG + BSTG)         // 46080
#define SMEM_GEMM (2 * STG)          // 92160

__device__ __forceinline__ void load_stage(uint32_t sA, const char* Ag,
                                           const char* Bg, int chunk, int tid) {
    const uint32_t sB = sA + ASTG;
    const char* ga = Ag + (size_t)chunk * 128;
#pragma unroll
    for (int l = 0; l < 2; l++) {
        int u = tid + 256 * l;
        int r = u >> 3, q = u & 7;
        cp16(sA + r * PITCH + q * 16, ga + (size_t)r * KPADB + q * 16);
    }
    const char* gb = Bg + (size_t)chunk * 128;
#pragma unroll
    for (int l = 0; l < 8; l++) {
        int u = tid + 256 * l;
        int r = u >> 3, q = u & 7;
        cp16(sB + r * PITCH + q * 16, gb + (size_t)r * KPADB + q * 16);
    }
}

__global__ __launch_bounds__(256, 2)
void encoder_mma(const float* __restrict__ b1, float* __restrict__ enc) {
    extern __shared__ char smraw[];
    const uint32_t smb = smem_to_u32(smraw);

    const int tid  = threadIdx.x;
    const int wid  = tid >> 5;
    const int lane = tid & 31;
    const int wm   = (wid & 1) * 32;
    const int wn   = (wid >> 1) * 64;
    const int m0   = blockIdx.y * 64;
    const int n0   = blockIdx.x * 256;

    const char* Ag = (const char*)(g_X3 + (size_t)m0 * KPAD);
    const char* Bg = (const char*)(g_W3 + (size_t)n0 * KPAD);

    float acc[64];
#pragma unroll
    for (int i = 0; i < 64; i++) acc[i] = 0.0f;

    load_stage(smb, Ag, Bg, 0, tid);
    CP_COMMIT();

    const uint32_t a_row = (lane & 7) + 8 * ((lane >> 3) & 1);
    const uint32_t a_kof = ((lane >> 4) << 3);
    const uint32_t b_row = (lane & 7) + 8 * ((lane >> 4) & 1);
    const uint32_t b_kof = ((lane >> 3) & 1) << 3;

    for (int c = 0; c < KCHUNKS; c++) {
        if (c + 1 < KCHUNKS) {
            load_stage(smb + (uint32_t)((c + 1) & 1) * STG, Ag, Bg, c + 1, tid);
            CP_COMMIT();
            CP_WAIT1();
        } else {
            CP_WAIT0();
        }
        __syncthreads();

        const uint32_t sA = smb + (uint32_t)(c & 1) * STG;
        const uint32_t sB = sA + ASTG;
#pragma unroll
        for (int h = 0; h < 4; h++) {
            const uint32_t k0 = h * 16;
            uint32_t a[2][4];
#pragma unroll
            for (int mi = 0; mi < 2; mi++)
                ldsm_x4(a[mi], sA + (wm + 16 * mi + a_row) * PITCH + (k0 + a_kof) * 2);
#pragma unroll
            for (int nb = 0; nb < 4; nb++) {
                uint32_t b[4];
                ldsm_x4(b, sB + (wn + 16 * nb + b_row) * PITCH + (k0 + b_kof) * 2);
#pragma unroll
                for (int mi = 0; mi < 2; mi++) {
                    mma_bf16(acc + (mi * 8 + 2 * nb) * 4,     a[mi], b[0], b[1]);
                    mma_bf16(acc + (mi * 8 + 2 * nb + 1) * 4, a[mi], b[2], b[3]);
                }
            }
        }
        __syncthreads();
    }

    const int rg = lane >> 2;
    const int cg = (lane & 3) * 2;
#pragma unroll
    for (int mi = 0; mi < 2; mi++) {
#pragma unroll
        for (int ni = 0; ni < 8; ni++) {
            const float* a4 = acc + (mi * 8 + ni) * 4;
            const int n = n0 + wn + 8 * ni + cg;
            const float2 bias = *(const float2*)(b1 + n);
            const int m = m0 + wm + 16 * mi + rg;
            float2 o0 = make_float2(a4[0] + bias.x, a4[1] + bias.y);
            float2 o1 = make_float2(a4[2] + bias.x, a4[3] + bias.y);
            *(float2*)(enc + (size_t)m * NDIM + n)       = o0;
            *(float2*)(enc + (size_t)(m + 8) * NDIM + n) = o1;
        }
    }
}

// ---------------- K2: fused topk (3-round radix) + sparse res + fp16 decoder --
// Radix resolves the top 24 bits of the rank-65 |value|; the recompute window
// covers [prefix, prefix|0xFF] +- MARGIN, so exactness is preserved while one
// histogram round is removed. Decoder reads the fp16 W^T copy (half traffic).
#define MARGIN 1e-4f

__global__ __launch_bounds__(512, 3)
void topk_dec_kernel(float* __restrict__ enc, float* __restrict__ res,
                     const float* __restrict__ x, const float* __restrict__ b1,
                     const float* __restrict__ b2, float* __restrict__ dec) {
    const int row = blockIdx.x;
    const int tid = threadIdx.x;
    const int lane = tid & 31;
    const int wid  = tid >> 5;
    float* er = enc + (size_t)row * NDIM;

    // element n for slot (i,j) = (tid + 512*i)*4 + j
    unsigned ab[8];
    unsigned sgn = 0;
    {
        const uint4* erv = (const uint4*)er;
#pragma unroll
        for (int i = 0; i < 2; i++) {
            uint4 u = erv[tid + 512 * i];
            ab[4 * i + 0] = u.x & 0x7fffffffu; sgn |= (u.x >> 31) << (4 * i + 0);
            ab[4 * i + 1] = u.y & 0x7fffffffu; sgn |= (u.y >> 31) << (4 * i + 1);
            ab[4 * i + 2] = u.z & 0x7fffffffu; sgn |= (u.z >> 31) << (4 * i + 2);
            ab[4 * i + 3] = u.w & 0x7fffffffu; sgn |= (u.w >> 31) << (4 * i + 3);
        }
    }

    __shared__ unsigned hist[256];
    __shared__ unsigned s_pref, s_want, s_thr;
    __shared__ int s_pack[16];
    __shared__ int s_A, s_C;
    __shared__ int s_nc;
    __shared__ unsigned s_list[512];
    __shared__ int s_slot;
    __shared__ int   s_idx2[96];
    __shared__ float s_val2[96];

    // ---- radix-256, 3 rounds: top-24 bits of the 65th-largest |value| ----
    unsigned prefix = 0, want = 65;
#pragma unroll
    for (int sh = 24; sh >= 8; sh -= 8) {
        if (tid < 256) hist[tid] = 0;
        __syncthreads();
        const unsigned mask = (sh == 24) ? 0u : (0xFFFFFFFFu << (sh + 8));
#pragma unroll
        for (int i = 0; i < 8; i++)
            if ((ab[i] & mask) == prefix)
                atomicAdd(&hist[(ab[i] >> sh) & 255u], 1u);
        __syncthreads();
        if (wid == 0) {
            unsigned part = 0;
#pragma unroll
            for (int j = 0; j < 8; j++) part += hist[lane * 8 + j];
            unsigned suf = part;
#pragma unroll
            for (int o = 1; o < 32; o <<= 1) {
                unsigned t2 = __shfl_down_sync(0xffffffffu, suf, o);
                if (lane + o < 32) suf += t2;
            }
            unsigned sufNext = __shfl_down_sync(0xffffffffu, suf, 1);
            if (lane == 31) sufNext = 0;
            unsigned bal = __ballot_sync(0xffffffffu, suf >= want);
            int L = 31 - __clz(bal);
            if (lane == L) {
                unsigned cumAbove = sufNext;
                int digit = 0;
                for (int j = 7; j >= 0; j--) {
                    unsigned h = hist[L * 8 + j];
                    if (cumAbove + h >= want) { digit = L * 8 + j; break; }
                    cumAbove += h;
                }
                s_pref = prefix | ((unsigned)digit << sh);
                s_want = want - cumAbove;
            }
        }
        __syncthreads();
        prefix = s_pref;
        want   = s_want;
    }
    // rank-65 GEMM |value| lies in [prefix, prefix + 0x100)
    const float TloF = __uint_as_float(prefix) - MARGIN;
    const float ThiF = __uint_as_float(prefix | 0xFFu) + MARGIN;

    // ---- count above-window / in-window ----
    int localA = 0, localC = 0;
#pragma unroll
    for (int i = 0; i < 8; i++) {
        float av = __uint_as_float(ab[i]);
        if (av > ThiF) localA++;
        else if (av >= TloF) localC++;
    }
    int packed = localA | (localC << 16);
#pragma unroll
    for (int o = 16; o; o >>= 1) packed += __shfl_xor_sync(0xffffffffu, packed, o);
    if (lane == 0) s_pack[wid] = packed;
    __syncthreads();
    if (tid == 0) {
        int t = 0;
#pragma unroll
        for (int w = 0; w < 16; w++) t += s_pack[w];
        s_A = t & 0xffff;
        s_C = t >> 16;
        s_nc = 0;
        s_slot = 0;
        s_thr = 0u;
    }
    __syncthreads();

    if (s_C > 1) {
        // ---- boundary recompute (round-1 summation order), exact select ----
        const float* xr = x + (size_t)row * KDIM;
#pragma unroll
        for (int i = 0; i < 8; i++) {
            float av = __uint_as_float(ab[i]);
            if (av >= TloF && av <= ThiF) {
                const int n = (tid + 512 * (i >> 2)) * 4 + (i & 3);
                const float* wt = g_Wt + (size_t)n * KDIM;
                float s = 0.0f;
                for (int d = 0; d < KDIM; d++) s = fmaf(xr[d], wt[d], s);
                s = s + b1[n];                   // bias LAST, plain add
                unsigned u = __float_as_uint(s);
                ab[i] = u & 0x7fffffffu;
                sgn = (sgn & ~(1u << i)) | ((u >> 31) << i);
                er[n] = s;
                int p = atomicAdd(&s_nc, 1);
                if (p < 512) s_list[p] = ab[i];
            }
        }
        __syncthreads();
        if (tid == 0) {
            int A = s_A;
            int L = s_nc < 512 ? s_nc : 512;
            int k = 65 - A;
            if (k < 1) k = 1;
            if (k > L) k = L;
            unsigned thr = 0;
            for (int it = 0; it < k; it++) {
                unsigned mx = 0; int mi = 0;
                for (int j = 0; j < L; j++)
                    if (s_list[j] > mx) { mx = s_list[j]; mi = j; }
                s_list[mi] = 0;
                thr = mx;
            }
            s_thr = thr;
        }
        __syncthreads();
    } else {
        // exactly one candidate in the window -> it IS rank-65; T = its bits
        if (tid == 0) s_thr = 0u;
        __syncthreads();
#pragma unroll
        for (int i = 0; i < 8; i++) {
            float av = __uint_as_float(ab[i]);
            if (av >= TloF && av <= ThiF) atomicMax(&s_thr, ab[i]);
        }
        __syncthreads();
    }
    const unsigned T = s_thr;

    // ---- sparse res write + compact (res pre-zeroed by memset) ----
    float* rr = res + (size_t)row * NDIM;
#pragma unroll
    for (int i = 0; i < 8; i++) {
        if (ab[i] > T) {
            const int n = (tid + 512 * (i >> 2)) * 4 + (i & 3);
            float vv = __uint_as_float(ab[i] | (((sgn >> i) & 1u) << 31));
            rr[n] = vv;
            int s = atomicAdd(&s_slot, 1);
            if (s < 96) { s_idx2[s] = n; s_val2[s] = vv; }
        }
    }
    __syncthreads();
    const int c = s_slot;
    if (tid == 0) atomicAdd(&g_total, c);

    // ---- fused sparse decoder (fp16 W^T, half the L2 traffic) ----
    const int d0 = tid, d1 = tid + 512;
    const bool has1 = (d1 < KDIM);
    float a0 = b2[d0];
    float a1 = has1 ? b2[d1] : 0.0f;
#pragma unroll 4
    for (int j = 0; j < c; j++) {
        const __half* wr = g_Wh + (size_t)s_idx2[j] * KDIM;
        const float val = s_val2[j];
        a0 = fmaf(val, __half2float(wr[d0]), a0);
        if (has1) a1 = fmaf(val, __half2float(wr[d1]), a1);
    }
    float* dr = dec + (size_t)row * KDIM;
    dr[d0] = a0;
    if (has1) dr[d1] = a1;
}

// ---------------- K3: nnz scalar ----------------
__global__ void nnz_kernel(float* __restrict__ nnz_out) {
    nnz_out[0] = (float)g_total / (float)B_ROWS;
}

// ---------------- launch ----------------
extern "C" void kernel_launch(void* const* d_in, const int* in_sizes, int n_in,
                              void* d_out, int out_size) {
    const float* x  = (const float*)d_in[0];
    const float* W  = (const float*)d_in[1];
    const float* b1 = (const float*)d_in[2];
    const float* b2 = (const float*)d_in[3];

    float* out = (float*)d_out;
    float* enc = out;                                        // 16384*4096
    float* dec = out + (size_t)B_ROWS * NDIM;                // 16384*784
    float* nnz = dec + (size_t)B_ROWS * KDIM;                // 1
    float* res = nnz + 1;                                    // 16384*4096

    cudaFuncSetAttribute(encoder_mma, cudaFuncAttributeMaxDynamicSharedMemorySize,
                         SMEM_GEMM);

    cudaMemsetAsync(res, 0, (size_t)B_ROWS * NDIM * sizeof(float));
    split_wt<<<dim3(NDIM / 64, (KDIM + 31) / 32), 256>>>(W);
    split_x<<<(B_ROWS * 394 + 255) / 256, 256>>>(x);
    encoder_mma<<<dim3(NDIM / 256, B_ROWS / 64), 256, SMEM_GEMM>>>(b1, enc);
    topk_dec_kernel<<<B_ROWS, 512>>>(enc, res, x, b1, b2, dec);
    nnz_kernel<<<1, 1>>>(nnz);
}

// round 16
// speedup vs baseline: 1.0596x; 1.0596x over previous
#include <cuda_runtime.h>
#include <cuda_bf16.h>
#include <cstdint>

#define B_ROWS 16384
#define NDIM   4096
#define KDIM   784
#define TOPK   64
#define KPAD   2368        // 3*784 = 2352 padded to 2368 = 37*64
#define KCHUNKS 37         // KPAD / 64
#define KPADB  (KPAD * 2)  // row bytes of bf16 expanded arrays

// ---- scratch (static device globals; no allocations allowed) ----
__device__ __nv_bfloat16 g_X3[(size_t)B_ROWS * KPAD];   // 77.6 MB
__device__ __nv_bfloat16 g_W3[(size_t)NDIM * KPAD];     // 19.4 MB
__device__ float g_Wt[NDIM * KDIM];                     // fp32 W^T
__device__ int   g_total;

// ================= PTX helpers =================
__device__ __forceinline__ uint32_t smem_to_u32(const void* p) {
    uint32_t a;
    asm("{ .reg .u64 t; cvta.to.shared.u64 t, %1; cvt.u32.u64 %0, t; }"
        : "=r"(a) : "l"(p));
    return a;
}
__device__ __forceinline__ void cp16(uint32_t dst, const void* src) {
    asm volatile("cp.async.cg.shared.global [%0], [%1], 16;" :: "r"(dst), "l"(src));
}
#define CP_COMMIT() asm volatile("cp.async.commit_group;" ::: "memory")
#define CP_WAIT1()  asm volatile("cp.async.wait_group 1;" ::: "memory")
#define CP_WAIT0()  asm volatile("cp.async.wait_group 0;" ::: "memory")

__device__ __forceinline__ void ldsm_x4(uint32_t* r, uint32_t addr) {
    asm volatile("ldmatrix.sync.aligned.m8n8.x4.shared.b16 {%0,%1,%2,%3}, [%4];"
                 : "=r"(r[0]), "=r"(r[1]), "=r"(r[2]), "=r"(r[3]) : "r"(addr));
}
__device__ __forceinline__ void mma_bf16(float* c, const uint32_t* a,
                                         uint32_t b0, uint32_t b1) {
    asm volatile(
        "mma.sync.aligned.m16n8k16.row.col.f32.bf16.bf16.f32 "
        "{%0,%1,%2,%3}, {%4,%5,%6,%7}, {%8,%9}, {%0,%1,%2,%3};"
        : "+f"(c[0]), "+f"(c[1]), "+f"(c[2]), "+f"(c[3])
        : "r"(a[0]), "r"(a[1]), "r"(a[2]), "r"(a[3]), "r"(b0), "r"(b1));
}

// ================= bf16 2-limb split =================
__device__ __forceinline__ void split2(float a, __nv_bfloat16& h0, __nv_bfloat16& h1) {
    h0 = __float2bfloat16(a);
    h1 = __float2bfloat16(a - __bfloat162float(h0));
}

// ---------------- P0: split x -> X3 ----------------
__global__ __launch_bounds__(256) void split_x(const float* __restrict__ x) {
    int idx = blockIdx.x * 256 + threadIdx.x;
    int m = idx / 394;
    int u = idx - m * 394;
    if (m >= B_ROWS) return;
    char* rowp = (char*)g_X3 + (size_t)m * KPADB;
    if (u < 392) {
        int k = 2 * u;
        float2 xv = *(const float2*)(x + (size_t)m * KDIM + k);
        __nv_bfloat16 a0, a1, c0, c1;
        split2(xv.x, a0, a1);
        split2(xv.y, c0, c1);
        __nv_bfloat162* p = (__nv_bfloat162*)(rowp + 12 * u);
        p[0] = __halves2bfloat162(a0, a1);
        p[1] = __halves2bfloat162(a0, c0);
        p[2] = __halves2bfloat162(c1, c0);
    } else {
        *(uint4*)(rowp + 4704 + (u - 392) * 16) = make_uint4(0, 0, 0, 0);
    }
}

// ---------------- P1: split W -> W3 + fp32 transpose (smem-tiled) ----------
__global__ __launch_bounds__(256) void split_wt(const float* __restrict__ W) {
    __shared__ float tile[32][65];
    const int n0  = blockIdx.x * 64;
    const int k0  = blockIdx.y * 32;
    const int tid = threadIdx.x;

    {
        const int c  = tid & 63;
        const int r0 = tid >> 6;
#pragma unroll
        for (int i = 0; i < 8; i++) {
            int r = r0 + 4 * i;
            int k = k0 + r;
            tile[r][c] = (k < KDIM) ? W[(size_t)k * NDIM + n0 + c] : 0.0f;
        }
    }
    __syncthreads();

    const int wrp  = tid >> 5;
    const int lane = tid & 31;
#pragma unroll
    for (int it = 0; it < 8; it++) {
        const int nl = wrp * 8 + it;
        const int n  = n0 + nl;
        char* rowp = (char*)g_W3 + (size_t)n * KPADB;

        if (k0 + lane < KDIM)
            g_Wt[(size_t)n * KDIM + k0 + lane] = tile[lane][nl];

#pragma unroll
        for (int rr = 0; rr < 2; rr++) {
            int w = lane + 32 * rr;
            if (w < 48 && (k0 * 6 + w * 4) < KPADB) {
                int p = w / 3, j = w - 3 * p;
                float w0 = tile[2 * p][nl];
                float w1 = tile[2 * p + 1][nl];
                __nv_bfloat16 b0, b1, d0, d1;
                split2(w0, b0, b1);
                split2(w1, d0, d1);
                __nv_bfloat162 val;
                if (j == 0)      val = __halves2bfloat162(b0, b0);
                else if (j == 1) val = __halves2bfloat162(b1, d0);
                else             val = __halves2bfloat162(d0, d1);
                *(__nv_bfloat162*)(rowp + k0 * 6 + w * 4) = val;
            }
        }
    }
    if (blockIdx.x == 0 && blockIdx.y == 0 && tid == 0) g_total = 0;
}

// ---------------- K1: encoder GEMM: CTA 64x128, 128 threads, 4 CTAs/SM ------
#define PITCH  144u
#define ASTG   (64u * PITCH)         // 9216
#define BSTG   (128u * PITCH)        // 18432
#define STG    (ASTG + BSTG)         // 27648
#define SMEM_GEMM (2 * STG)          // 55296

__device__ __forceinline__ void load_stage(uint32_t sA, const char* Ag,
                                           const char* Bg, int chunk, int tid) {
    const uint32_t sB = sA + ASTG;
    const char* ga = Ag + (size_t)chunk * 128;
#pragma unroll
    for (int l = 0; l < 4; l++) {
        int u = tid + 128 * l;
        int r = u >> 3, q = u & 7;
        cp16(sA + r * PITCH + q * 16, ga + (size_t)r * KPADB + q * 16);
    }
    const char* gb = Bg + (size_t)chunk * 128;
#pragma unroll
    for (int l = 0; l < 8; l++) {
        int u = tid + 128 * l;
        int r = u >> 3, q = u & 7;
        cp16(sB + r * PITCH + q * 16, gb + (size_t)r * KPADB + q * 16);
    }
}

__global__ __launch_bounds__(128, 4)
void encoder_mma(const float* __restrict__ b1, float* __restrict__ enc) {
    extern __shared__ char smraw[];
    const uint32_t smb = smem_to_u32(smraw);

    const int tid  = threadIdx.x;
    const int wid  = tid >> 5;
    const int lane = tid & 31;
    const int wm   = (wid & 1) * 32;     // warp m offset within 64
    const int wn   = (wid >> 1) * 64;    // warp n offset within 128
    const int m0   = blockIdx.y * 64;
    const int n0   = blockIdx.x * 128;

    const char* Ag = (const char*)(g_X3 + (size_t)m0 * KPAD);
    const char* Bg = (const char*)(g_W3 + (size_t)n0 * KPAD);

    float acc[64];
#pragma unroll
    for (int i = 0; i < 64; i++) acc[i] = 0.0f;

    load_stage(smb, Ag, Bg, 0, tid);
    CP_COMMIT();

    const uint32_t a_row = (lane & 7) + 8 * ((lane >> 3) & 1);
    const uint32_t a_kof = ((lane >> 4) << 3);
    const uint32_t b_row = (lane & 7) + 8 * ((lane >> 4) & 1);
    const uint32_t b_kof = ((lane >> 3) & 1) << 3;

    for (int c = 0; c < KCHUNKS; c++) {
        if (c + 1 < KCHUNKS) {
            load_stage(smb + (uint32_t)((c + 1) & 1) * STG, Ag, Bg, c + 1, tid);
            CP_COMMIT();
            CP_WAIT1();
        } else {
            CP_WAIT0();
        }
        __syncthreads();

        const uint32_t sA = smb + (uint32_t)(c & 1) * STG;
        const uint32_t sB = sA + ASTG;
#pragma unroll
        for (int h = 0; h < 4; h++) {
            const uint32_t k0 = h * 16;
            uint32_t a[2][4];
#pragma unroll
            for (int mi = 0; mi < 2; mi++)
                ldsm_x4(a[mi], sA + (wm + 16 * mi + a_row) * PITCH + (k0 + a_kof) * 2);
#pragma unroll
            for (int nb = 0; nb < 4; nb++) {
                uint32_t b[4];
                ldsm_x4(b, sB + (wn + 16 * nb + b_row) * PITCH + (k0 + b_kof) * 2);
#pragma unroll
                for (int mi = 0; mi < 2; mi++) {
                    mma_bf16(acc + (mi * 8 + 2 * nb) * 4,     a[mi], b[0], b[1]);
                    mma_bf16(acc + (mi * 8 + 2 * nb + 1) * 4, a[mi], b[2], b[3]);
                }
            }
        }
        __syncthreads();
    }

    const int rg = lane >> 2;
    const int cg = (lane & 3) * 2;
#pragma unroll
    for (int mi = 0; mi < 2; mi++) {
#pragma unroll
        for (int ni = 0; ni < 8; ni++) {
            const float* a4 = acc + (mi * 8 + ni) * 4;
            const int n = n0 + wn + 8 * ni + cg;
            const float2 bias = *(const float2*)(b1 + n);
            const int m = m0 + wm + 16 * mi + rg;
            float2 o0 = make_float2(a4[0] + bias.x, a4[1] + bias.y);
            float2 o1 = make_float2(a4[2] + bias.x, a4[3] + bias.y);
            *(float2*)(enc + (size_t)m * NDIM + n)       = o0;
            *(float2*)(enc + (size_t)(m + 8) * NDIM + n) = o1;
        }
    }
}

// ---------------- K2: fused topk + sparse res + decoder (R14, measured best) -
#define MARGIN 1e-4f

__global__ __launch_bounds__(512, 3)
void topk_dec_kernel(float* __restrict__ enc, float* __restrict__ res,
                     const float* __restrict__ x, const float* __restrict__ b1,
                     const float* __restrict__ b2, float* __restrict__ dec) {
    const int row = blockIdx.x;
    const int tid = threadIdx.x;
    const int lane = tid & 31;
    const int wid  = tid >> 5;
    float* er = enc + (size_t)row * NDIM;

    // element n for slot (i,j) = (tid + 512*i)*4 + j
    unsigned ab[8];
    unsigned sgn = 0;
    {
        const uint4* erv = (const uint4*)er;
#pragma unroll
        for (int i = 0; i < 2; i++) {
            uint4 u = erv[tid + 512 * i];
            ab[4 * i + 0] = u.x & 0x7fffffffu; sgn |= (u.x >> 31) << (4 * i + 0);
            ab[4 * i + 1] = u.y & 0x7fffffffu; sgn |= (u.y >> 31) << (4 * i + 1);
            ab[4 * i + 2] = u.z & 0x7fffffffu; sgn |= (u.z >> 31) << (4 * i + 2);
            ab[4 * i + 3] = u.w & 0x7fffffffu; sgn |= (u.w >> 31) << (4 * i + 3);
        }
    }

    __shared__ unsigned hist[256];
    __shared__ unsigned s_pref, s_want, s_thr;
    __shared__ int s_pack[16];
    __shared__ int s_A, s_C;
    __shared__ int s_nc;
    __shared__ unsigned s_list[512];
    __shared__ int s_slot;
    __shared__ int   s_idx2[96];
    __shared__ float s_val2[96];

    // ---- radix-256: exact 65th-largest |value| ----
    unsigned prefix = 0, want = 65;
#pragma unroll
    for (int sh = 24; sh >= 0; sh -= 8) {
        if (tid < 256) hist[tid] = 0;
        __syncthreads();
        const unsigned mask = (sh == 24) ? 0u : (0xFFFFFFFFu << (sh + 8));
#pragma unroll
        for (int i = 0; i < 8; i++)
            if ((ab[i] & mask) == prefix)
                atomicAdd(&hist[(ab[i] >> sh) & 255u], 1u);
        __syncthreads();
        if (wid == 0) {
            unsigned part = 0;
#pragma unroll
            for (int j = 0; j < 8; j++) part += hist[lane * 8 + j];
            unsigned suf = part;
#pragma unroll
            for (int o = 1; o < 32; o <<= 1) {
                unsigned t2 = __shfl_down_sync(0xffffffffu, suf, o);
                if (lane + o < 32) suf += t2;
            }
            unsigned sufNext = __shfl_down_sync(0xffffffffu, suf, 1);
            if (lane == 31) sufNext = 0;
            unsigned bal = __ballot_sync(0xffffffffu, suf >= want);
            int L = 31 - __clz(bal);
            if (lane == L) {
                unsigned cumAbove = sufNext;
                int digit = 0;
                for (int j = 7; j >= 0; j--) {
                    unsigned h = hist[L * 8 + j];
                    if (cumAbove + h >= want) { digit = L * 8 + j; break; }
                    cumAbove += h;
                }
                s_pref = prefix | ((unsigned)digit << sh);
                s_want = want - cumAbove;
            }
        }
        __syncthreads();
        prefix = s_pref;
        want   = s_want;
    }
    const float Tf = __uint_as_float(prefix);   // GEMM-value rank-65 threshold

    // ---- count above / in-window ----
    int localA = 0, localC = 0;
#pragma unroll
    for (int i = 0; i < 8; i++) {
        float av = __uint_as_float(ab[i]);
        if (av > Tf + MARGIN) localA++;
        else if (av >= Tf - MARGIN) localC++;
    }
    int packed = localA | (localC << 16);
#pragma unroll
    for (int o = 16; o; o >>= 1) packed += __shfl_xor_sync(0xffffffffu, packed, o);
    if (lane == 0) s_pack[wid] = packed;
    __syncthreads();
    if (tid == 0) {
        int t = 0;
#pragma unroll
        for (int w = 0; w < 16; w++) t += s_pack[w];
        s_A = t & 0xffff;
        s_C = t >> 16;
        s_nc = 0;
        s_slot = 0;
        s_thr = prefix;       // default: skip case keeps GEMM threshold
    }
    __syncthreads();

    if (s_C > 1) {
        // ---- boundary recompute (round-1 summation order) ----
        const float* xr = x + (size_t)row * KDIM;
#pragma unroll
        for (int i = 0; i < 8; i++) {
            float av = __uint_as_float(ab[i]);
            if (av >= Tf - MARGIN && av <= Tf + MARGIN) {
                const int n = (tid + 512 * (i >> 2)) * 4 + (i & 3);
                const float* wt = g_Wt + (size_t)n * KDIM;
                float s = 0.0f;
                for (int d = 0; d < KDIM; d++) s = fmaf(xr[d], wt[d], s);
                s = s + b1[n];                   // bias LAST, plain add
                unsigned u = __float_as_uint(s);
                ab[i] = u & 0x7fffffffu;
                sgn = (sgn & ~(1u << i)) | ((u >> 31) << i);
                er[n] = s;
                int p = atomicAdd(&s_nc, 1);
                if (p < 512) s_list[p] = ab[i];
            }
        }
        __syncthreads();
        if (tid == 0) {
            int A = s_A;
            int L = s_nc < 512 ? s_nc : 512;
            int k = 65 - A;
            if (k < 1) k = 1;
            if (k > L) k = L;
            unsigned thr = 0;
            for (int it = 0; it < k; it++) {
                unsigned mx = 0; int mi = 0;
                for (int j = 0; j < L; j++)
                    if (s_list[j] > mx) { mx = s_list[j]; mi = j; }
                s_list[mi] = 0;
                thr = mx;
            }
            s_thr = thr;
        }
        __syncthreads();
    }
    const unsigned T = s_thr;

    // ---- sparse res write + compact (res pre-zeroed by memset) ----
    float* rr = res + (size_t)row * NDIM;
#pragma unroll
    for (int i = 0; i < 8; i++) {
        if (ab[i] > T) {
            const int n = (tid + 512 * (i >> 2)) * 4 + (i & 3);
            float vv = __uint_as_float(ab[i] | (((sgn >> i) & 1u) << 31));
            rr[n] = vv;
            int s = atomicAdd(&s_slot, 1);
            if (s < 96) { s_idx2[s] = n; s_val2[s] = vv; }
        }
    }
    __syncthreads();
    const int c = s_slot;
    if (tid == 0) atomicAdd(&g_total, c);

    // ---- fused sparse decoder (fp32 W^T) ----
    const int d0 = tid, d1 = tid + 512;
    const bool has1 = (d1 < KDIM);
    float a0 = b2[d0];
    float a1 = has1 ? b2[d1] : 0.0f;
#pragma unroll 4
    for (int j = 0; j < c; j++) {
        const float* wr = g_Wt + (size_t)s_idx2[j] * KDIM;
        const float val = s_val2[j];
        a0 = fmaf(val, wr[d0], a0);
        if (has1) a1 = fmaf(val, wr[d1], a1);
    }
    float* dr = dec + (size_t)row * KDIM;
    dr[d0] = a0;
    if (has1) dr[d1] = a1;
}

// ---------------- K3: nnz scalar ----------------
__global__ void nnz_kernel(float* __restrict__ nnz_out) {
    nnz_out[0] = (float)g_total / (float)B_ROWS;
}

// ---------------- launch ----------------
extern "C" void kernel_launch(void* const* d_in, const int* in_sizes, int n_in,
                              void* d_out, int out_size) {
    const float* x  = (const float*)d_in[0];
    const float* W  = (const float*)d_in[1];
    const float* b1 = (const float*)d_in[2];
    const float* b2 = (const float*)d_in[3];

    float* out = (float*)d_out;
    float* enc = out;                                        // 16384*4096
    float* dec = out + (size_t)B_ROWS * NDIM;                // 16384*784
    float* nnz = dec + (size_t)B_ROWS * KDIM;                // 1
    float* res = nnz + 1;                                    // 16384*4096

    cudaFuncSetAttribute(encoder_mma, cudaFuncAttributeMaxDynamicSharedMemorySize,
                         SMEM_GEMM);

    cudaMemsetAsync(res, 0, (size_t)B_ROWS * NDIM * sizeof(float));
    split_wt<<<dim3(NDIM / 64, (KDIM + 31) / 32), 256>>>(W);
    split_x<<<(B_ROWS * 394 + 255) / 256, 256>>>(x);
    encoder_mma<<<dim3(NDIM / 128, B_ROWS / 64), 128, SMEM_GEMM>>>(b1, enc);
    topk_dec_kernel<<<B_ROWS, 512>>>(enc, res, x, b1, b2, dec);
    nnz_kernel<<<1, 1>>>(nnz);
}